// round 13
// baseline (speedup 1.0000x reference)
#include <cuda_runtime.h>
#include <cuda_fp16.h>
#include <math.h>

// Problem constants
#define BB    4
#define NN    1024
#define DD    512
#define HH    8
#define HDIM  64
#define EE    4
#define LL    3
#define MTOT  (BB*NN)   // 4096

#define EBPLANE ((size_t)BB*HH*NN*NN)   // elements per layer bias plane
#define LOG2E 1.44269504f

// Scratch: h fp32 8MB | q,k,vt,att half 16MB | weights ~6.4MB | 3 bias planes 201MB
__device__ __align__(256) unsigned char g_scratch[232914944];

// ---------------------------------------------------------------------------
// Helpers
// ---------------------------------------------------------------------------
__device__ __forceinline__ unsigned packh2(float lo, float hi) {
    __half2 h = __floats2half2_rn(lo, hi);
    return *reinterpret_cast<unsigned*>(&h);
}

__device__ __forceinline__ void mma_f16(float c[4], const unsigned a[4],
                                        unsigned b0, unsigned b1) {
    asm volatile(
        "mma.sync.aligned.m16n8k16.row.col.f32.f16.f16.f32 "
        "{%0,%1,%2,%3}, {%4,%5,%6,%7}, {%8,%9}, {%0,%1,%2,%3};\n"
        : "+f"(c[0]), "+f"(c[1]), "+f"(c[2]), "+f"(c[3])
        : "r"(a[0]), "r"(a[1]), "r"(a[2]), "r"(a[3]), "r"(b0), "r"(b1));
}

__device__ __forceinline__ void cp16(unsigned dst, const void* src) {
    asm volatile("cp.async.cg.shared.global [%0], [%1], 16;\n"
                 :: "r"(dst), "l"(src));
}
#define CP_COMMIT() asm volatile("cp.async.commit_group;\n" ::: "memory")
#define CP_WAIT(N)  asm volatile("cp.async.wait_group %0;\n" :: "n"(N) : "memory")

// ---------------------------------------------------------------------------
// Weight transpose + fp16 convert: dst[n][k] = (half)src[k][n], 32x32 tiles
// ---------------------------------------------------------------------------
__device__ __forceinline__ void transpose_body(
    const float* __restrict__ src, __half* __restrict__ dst, int K, int N)
{
    __shared__ float t[32][33];
    const int k0 = blockIdx.y * 32, n0 = blockIdx.x * 32;
    const int c = threadIdx.x & 31, r0 = threadIdx.x >> 5;
#pragma unroll
    for (int i = 0; i < 4; i++) {
        int r = r0 + i * 8;
        t[r][c] = src[(size_t)(k0 + r) * N + n0 + c];
    }
    __syncthreads();
#pragma unroll
    for (int i = 0; i < 4; i++) {
        int r = r0 + i * 8;
        dst[(size_t)(n0 + r) * K + k0 + c] = __float2half(t[c][r]);
    }
}

__global__ void transpose_w(const float* __restrict__ src,
                            __half* __restrict__ dst, int K, int N)
{
    transpose_body(src, dst, K, N);
}

__global__ void transpose_w4(
    const float* __restrict__ sq, const float* __restrict__ sk,
    const float* __restrict__ sv, const float* __restrict__ so,
    __half* __restrict__ dq, __half* __restrict__ dk,
    __half* __restrict__ dv, __half* __restrict__ dw)
{
    const int z = blockIdx.z, g = z / 3, l = z % 3;
    const size_t off = (size_t)l * DD * DD;
    const float* src = ((g == 0) ? sq : (g == 1) ? sk : (g == 2) ? sv : so) + off;
    __half* dst = ((g == 0) ? dq : (g == 1) ? dk : (g == 2) ? dv : dw) + off;
    transpose_body(src, dst, DD, DD);
}

// ---------------------------------------------------------------------------
// Fused edge-bias precompute for ALL 3 layers, scaled by LOG2E
// ---------------------------------------------------------------------------
__global__ __launch_bounds__(256) void edgebias3(
    const float* __restrict__ edges, const float* __restrict__ ew,
    __half* __restrict__ eb)
{
    __shared__ float sew[LL * EE * HH];   // 96
    const int tid = threadIdx.x;
    if (tid < LL * EE * HH) sew[tid] = ew[tid] * LOG2E;
    __syncthreads();
    const int i = blockIdx.x, b = blockIdx.y;
    const int j0 = tid << 2;
    const float* ep = edges + (((size_t)b * NN + i) * NN + j0) * EE;
    float4 e[4];
#pragma unroll
    for (int t = 0; t < 4; t++) e[t] = *(const float4*)(ep + t * EE);
#pragma unroll
    for (int l = 0; l < LL; l++) {
        const float* w = sew + l * EE * HH;
#pragma unroll
        for (int hh = 0; hh < HH; hh++) {
            const float w0 = w[0 * HH + hh], w1 = w[1 * HH + hh];
            const float w2 = w[2 * HH + hh], w3 = w[3 * HH + hh];
            float bv[4];
#pragma unroll
            for (int t = 0; t < 4; t++)
                bv[t] = e[t].x * w0 + e[t].y * w1 + e[t].z * w2 + e[t].w * w3;
            __half* dst = eb + (size_t)l * EBPLANE +
                          (((size_t)(b * HH + hh)) * NN + i) * NN + j0;
            *(uint2*)dst =
                make_uint2(packh2(bv[0], bv[1]), packh2(bv[2], bv[3]));
        }
    }
}

// ---------------------------------------------------------------------------
// fp16 GEMM: C[M,512] = A[M,K] @ Wh^T + bias (+resid), optional scale.
// BM = MHALF?64:128, BN=128, BK=32. 8 warps; warp tile (BM/4) x 64.
// MHALF=1 halves the block (better wave quantization for the QKV launch);
// accumulation order per output is unchanged -> bit-identical results.
// ---------------------------------------------------------------------------
#define AST 24
#define TWORDS (128*AST)

template<int AHALF, int MHALF>
__global__ __launch_bounds__(256, 2) void gemm_h(
    const void* __restrict__ Av,
    const __half* __restrict__ Wh0, const __half* __restrict__ Wh1,
    const __half* __restrict__ Wh2,
    const float* __restrict__ bs0, const float* __restrict__ bs1,
    const float* __restrict__ bs2,
    void* __restrict__ C0, void* __restrict__ C1, void* __restrict__ C2,
    const float* __restrict__ resid, int K, int chalf, int tindex,
    float scl0)
{
    __shared__ unsigned As[2][TWORDS];
    __shared__ unsigned Bs[2][TWORDS];

    const int z = blockIdx.z;
    const __half* Wh   = (z == 0) ? Wh0 : (z == 1) ? Wh1 : Wh2;
    const float*  bias = (z == 0) ? bs0 : (z == 1) ? bs1 : bs2;
    void*         C    = (z == 0) ? C0  : (z == 1) ? C1  : C2;
    const float   sc   = (z == 0) ? scl0 : 1.0f;

    const int tid = threadIdx.x;
    const int wid = tid >> 5, lane = tid & 31;
    const int wm = wid & 3, wn = wid >> 2;
    const int qr = lane >> 2, qc = lane & 3;
    const int BMv = MHALF ? 64 : 128;
    const int m0 = blockIdx.y * BMv, n0 = blockIdx.x * 128;
    const int KS = K >> 5;
    const int wmb = MHALF ? wm * 16 : wm * 32;
    const int NMF = MHALF ? 1 : 2;

    const int hr = tid >> 1, hg = tid & 1;
    const int fr = tid >> 2, fg = (tid >> 1) & 1, fq = tid & 1;

    float4 aA0, aB0, aA1, aB1;
    uint4  aL1, aL2;
    uint4  bL1, bL2;

#define LOAD_STAGE(k0)                                                        \
    do {                                                                      \
        if (AHALF) {                                                          \
            const __half* Ah = (const __half*)Av +                            \
                (size_t)(m0 + hr) * K + (k0) + hg * 16;                       \
            aL1 = *(const uint4*)Ah; aL2 = *(const uint4*)(Ah + 8);           \
        } else {                                                              \
            const float* Af = (const float*)Av +                              \
                (size_t)(m0 + fr) * K + (k0) + fg * 16 + fq * 4;              \
            aA0 = *(const float4*)Af; aB0 = *(const float4*)(Af + 8);         \
            if (!MHALF) {                                                     \
                const float* Ag = Af + (size_t)64 * K;                        \
                aA1 = *(const float4*)Ag; aB1 = *(const float4*)(Ag + 8);     \
            }                                                                 \
        }                                                                     \
        const __half* Bp = Wh + (size_t)(n0 + hr) * K + (k0) + hg * 16;       \
        bL1 = *(const uint4*)Bp; bL2 = *(const uint4*)(Bp + 8);               \
    } while (0)

#define STORE_STAGE(buf)                                                      \
    do {                                                                      \
        if (AHALF) {                                                          \
            unsigned* p = &As[buf][hr * AST + hg * 8];                        \
            *(uint2*)(p + 0) = make_uint2(aL1.x, aL2.x);                      \
            *(uint2*)(p + 2) = make_uint2(aL1.y, aL2.y);                      \
            *(uint2*)(p + 4) = make_uint2(aL1.z, aL2.z);                      \
            *(uint2*)(p + 6) = make_uint2(aL1.w, aL2.w);                      \
        } else {                                                              \
            *(uint4*)&As[buf][fr * AST + fg * 8 + fq * 4] =                   \
                make_uint4(packh2(aA0.x, aA0.y), packh2(aB0.x, aB0.y),        \
                           packh2(aA0.z, aA0.w), packh2(aB0.z, aB0.w));       \
            if (!MHALF)                                                       \
                *(uint4*)&As[buf][(fr + 64) * AST + fg * 8 + fq * 4] =        \
                    make_uint4(packh2(aA1.x, aA1.y), packh2(aB1.x, aB1.y),    \
                               packh2(aA1.z, aA1.w), packh2(aB1.z, aB1.w));   \
        }                                                                     \
        unsigned* bp = &Bs[buf][hr * AST + hg * 8];                           \
        *(uint2*)(bp + 0) = make_uint2(bL1.x, bL2.x);                         \
        *(uint2*)(bp + 2) = make_uint2(bL1.y, bL2.y);                         \
        *(uint2*)(bp + 4) = make_uint2(bL1.z, bL2.z);                         \
        *(uint2*)(bp + 6) = make_uint2(bL1.w, bL2.w);                         \
    } while (0)

    LOAD_STAGE(0);
    STORE_STAGE(0);
    __syncthreads();

    float acc[MHALF ? 1 : 2][8][4] = {};

    for (int ks = 0; ks < KS; ks++) {
        const int nxt = ks + 1;
        if (nxt < KS) LOAD_STAGE(nxt << 5);

        const unsigned* Ab = As[ks & 1];
        const unsigned* Bb = Bs[ks & 1];
#pragma unroll
        for (int k16 = 0; k16 < 2; k16++) {
            unsigned af[MHALF ? 1 : 2][4];
#pragma unroll
            for (int mf = 0; mf < NMF; mf++) {
                const unsigned* ap =
                    &Ab[(wmb + mf * 16 + qr) * AST + k16 * 8 + 2 * qc];
                uint2 lo = *(const uint2*)ap;
                uint2 hi = *(const uint2*)(ap + 8 * AST);
                af[mf][0] = lo.x; af[mf][1] = hi.x;
                af[mf][2] = lo.y; af[mf][3] = hi.y;
            }
#pragma unroll
            for (int nf = 0; nf < 8; nf++) {
                uint2 bb = *(const uint2*)
                    &Bb[(wn * 64 + nf * 8 + qr) * AST + k16 * 8 + 2 * qc];
                mma_f16(acc[0][nf], af[0], bb.x, bb.y);
                if (!MHALF) mma_f16(acc[1][nf], af[1], bb.x, bb.y);
            }
        }
        if (nxt < KS) {
            __syncthreads();
            STORE_STAGE(nxt & 1);
            __syncthreads();
        }
    }

    const bool transp = (chalf && z == tindex);
#pragma unroll
    for (int mf = 0; mf < NMF; mf++) {
#pragma unroll
        for (int nf = 0; nf < 8; nf++) {
            const int col = n0 + wn * 64 + nf * 8 + 2 * qc;
            const float b0 = bias[col], b1 = bias[col + 1];
#pragma unroll
            for (int rr = 0; rr < 2; rr++) {
                const int row = m0 + wmb + mf * 16 + qr + rr * 8;
                float o0 = (acc[mf][nf][rr * 2 + 0] + b0) * sc;
                float o1 = (acc[mf][nf][rr * 2 + 1] + b1) * sc;
                if (!chalf) {
                    float* Cf = (float*)C;
                    if (resid) {
                        const float* rp = resid + (size_t)row * DD + col;
                        o0 += rp[0]; o1 += rp[1];
                    }
                    *(float2*)(Cf + (size_t)row * DD + col) =
                        make_float2(o0, o1);
                } else if (transp) {
                    // vt[col][perm(row)] - permute along token dimension
                    const int wr = row >> 1, ww = wr & 7;
                    const int pww = 2 * (ww & 3) + (ww >> 2);
                    const int prow = ((wr & ~7) + pww) * 2 + (row & 1);
                    __half* Ch = (__half*)C;
                    Ch[(size_t)col * MTOT + prow]       = __float2half(o0);
                    Ch[(size_t)(col + 1) * MTOT + prow] = __float2half(o1);
                } else {
                    __half* Ch = (__half*)C;
                    const int lw = nf * 4 + qc;
                    const int pw = 2 * (lw & 3) + ((lw & 4) >> 2);
                    const int pcol = n0 + wn * 64 + ((lw & ~7) + pw) * 2;
                    __half2 hv = __floats2half2_rn(o0, o1);
                    *(__half2*)(Ch + (size_t)row * DD + pcol) = hv;
                }
            }
        }
    }
#undef LOAD_STAGE
#undef STORE_STAGE
}

// ---------------------------------------------------------------------------
// fp16 flash attention (R12 winner, unchanged): cp.async double-buffered K/V,
// exp2-domain softmax w/o max tracking, P entirely in registers.
// ---------------------------------------------------------------------------
#define QST 40
#define KVW (64*QST)
#define ATTN_SMEM ((128*QST + 4*KVW) * 4)   // 61440 B

__global__ __launch_bounds__(256, 2) void attn_h(
    const __half* __restrict__ q, const __half* __restrict__ k,
    const __half* __restrict__ vt, const __half* __restrict__ eb,
    __half* __restrict__ out)
{
    extern __shared__ unsigned smx[];
    unsigned* Qs = smx;                    // [128][QST]
    unsigned* Ks = Qs + 128 * QST;         // [2][64][QST]
    unsigned* Vs = Ks + 2 * KVW;           // [2][64][QST]

    const int h = blockIdx.x, it = blockIdx.y, b = blockIdx.z;
    const int i0 = it << 7;
    const int tid = threadIdx.x;
    const int w = tid >> 5, lane = tid & 31;
    const int qr = lane >> 2, qc = lane & 3;

    const __half* qbase = q + (size_t)(b * NN + i0) * DD + h * HDIM;
    const __half* kbase = k + (size_t)(b * NN) * DD + h * HDIM;
    const __half* vtb = vt + (size_t)(h * HDIM) * MTOT + b * NN;

    const unsigned qs_b = (unsigned)__cvta_generic_to_shared(Qs);
    const unsigned ks_b = (unsigned)__cvta_generic_to_shared(Ks);
    const unsigned vs_b = (unsigned)__cvta_generic_to_shared(Vs);

    const int lrow = tid >> 2, lg = tid & 3;

#pragma unroll
    for (int i = 0; i < 2; i++) {
        const int t = tid + i * 256;
        const int row = t >> 2, g = t & 3;
        unsigned d = qs_b + (row * QST + g * 8) * 4;
        const __half* s = qbase + (size_t)row * DD + g * 16;
        cp16(d, s); cp16(d + 16, s + 8);
    }
    CP_COMMIT();
    {
        unsigned kd = ks_b + (lrow * QST + lg * 8) * 4;
        const __half* ksrc = kbase + (size_t)lrow * DD + lg * 16;
        cp16(kd, ksrc); cp16(kd + 16, ksrc + 8);
        unsigned vd = vs_b + (lrow * QST + lg * 8) * 4;
        const __half* vsrc = vtb + (size_t)lrow * MTOT + lg * 16;
        cp16(vd, vsrc); cp16(vd + 16, vsrc + 8);
    }
    CP_COMMIT();

    CP_WAIT(1);
    __syncthreads();

    unsigned qf[4][4];
#pragma unroll
    for (int g = 0; g < 4; g++) {
        const unsigned* qp = &Qs[(w * 16 + qr) * QST + g * 8 + 2 * qc];
        uint2 lo = *(const uint2*)qp;
        uint2 hi = *(const uint2*)(qp + 8 * QST);
        qf[g][0] = lo.x; qf[g][1] = hi.x;
        qf[g][2] = lo.y; qf[g][3] = hi.y;
    }

    float l0v = 0.f, l1v = 0.f;
    float of[8][4] = {};

    const int gi = i0 + w * 16 + qr;
    const __half* bp0 = eb + ((size_t)(b * HH + h) * NN + gi) * NN + 2 * qc;
    const __half* bp1 = bp0 + (size_t)8 * NN;

    for (int jt = 0; jt < 16; jt++) {
        const int j0 = jt << 6;
        CP_WAIT(0);
        __syncthreads();

        if (jt < 15) {
            const int st = (jt + 1) & 1;
            unsigned kd = ks_b + (st * KVW + lrow * QST + lg * 8) * 4;
            const __half* ksrc = kbase + (size_t)(j0 + 64 + lrow) * DD + lg * 16;
            cp16(kd, ksrc); cp16(kd + 16, ksrc + 8);
            unsigned vd = vs_b + (st * KVW + lrow * QST + lg * 8) * 4;
            const __half* vsrc = vtb + (size_t)lrow * MTOT + j0 + 64 + lg * 16;
            cp16(vd, vsrc); cp16(vd + 16, vsrc + 8);
            CP_COMMIT();
        }

        const unsigned* Kst = Ks + (jt & 1) * KVW;
        const unsigned* Vst = Vs + (jt & 1) * KVW;

        __half2 Bv0[8], Bv1[8];
#pragma unroll
        for (int n8 = 0; n8 < 8; n8++) {
            Bv0[n8] = *(const __half2*)(bp0 + j0 + n8 * 8);
            Bv1[n8] = *(const __half2*)(bp1 + j0 + n8 * 8);
        }

        // ---- S = Q K^T (log2 domain) + bias; p = exp2(S); pack to regs ----
        unsigned pf[8][2];
#pragma unroll
        for (int n8 = 0; n8 < 8; n8++) {
            float sd[4] = {};
            const unsigned* kp = &Kst[(n8 * 8 + qr) * QST + 2 * qc];
#pragma unroll
            for (int g = 0; g < 4; g++) {
                uint2 bb = *(const uint2*)(kp + g * 8);
                mma_f16(sd, qf[g], bb.x, bb.y);
            }
            float2 f0 = __half22float2(Bv0[n8]);
            float2 f1 = __half22float2(Bv1[n8]);
            float p0 = exp2f(sd[0] + f0.x);
            float p1 = exp2f(sd[1] + f0.y);
            float p2 = exp2f(sd[2] + f1.x);
            float p3 = exp2f(sd[3] + f1.y);
            l0v += p0 + p1;
            l1v += p2 + p3;
            pf[n8][0] = packh2(p0, p1);
            pf[n8][1] = packh2(p2, p3);
        }

        // ---- O += P @ V  (A-fragments straight from pf registers) ----
#pragma unroll
        for (int g = 0; g < 4; g++) {
            unsigned af[4];
            af[0] = pf[2 * g][0];
            af[1] = pf[2 * g][1];
            af[2] = pf[2 * g + 1][0];
            af[3] = pf[2 * g + 1][1];
#pragma unroll
            for (int n8 = 0; n8 < 8; n8++) {
                uint2 vv = *(const uint2*)
                    &Vst[(n8 * 8 + qr) * QST + g * 8 + 2 * qc];
                mma_f16(of[n8], af, vv.x, vv.y);
            }
        }
    }

    l0v += __shfl_xor_sync(0xffffffffu, l0v, 1);
    l0v += __shfl_xor_sync(0xffffffffu, l0v, 2);
    l1v += __shfl_xor_sync(0xffffffffu, l1v, 1);
    l1v += __shfl_xor_sync(0xffffffffu, l1v, 2);

    __half* obase = out + (size_t)(b * NN + i0 + w * 16 + qr) * DD + h * HDIM;
    const float inv0 = 1.0f / l0v, inv1 = 1.0f / l1v;
#pragma unroll
    for (int n8 = 0; n8 < 8; n8++) {
        const int col = n8 * 8 + (qc << 1);
        *(__half2*)(obase + col) =
            __floats2half2_rn(of[n8][0] * inv0, of[n8][1] * inv0);
        *(__half2*)(obase + (size_t)8 * DD + col) =
            __floats2half2_rn(of[n8][2] * inv1, of[n8][3] * inv1);
    }
}

// ---------------------------------------------------------------------------
// Row LayerNorm
// ---------------------------------------------------------------------------
__device__ __forceinline__ float warp_sum(float s) {
#pragma unroll
    for (int o = 16; o; o >>= 1) s += __shfl_xor_sync(0xffffffffu, s, o);
    return s;
}

__global__ __launch_bounds__(128) void ln_kernel(
    const float* __restrict__ hin, const float* __restrict__ gw,
    const float* __restrict__ gb, float* __restrict__ out)
{
    __shared__ float red[4];
    const int row = blockIdx.x;
    const int tid = threadIdx.x;
    const int wid = tid >> 5, lane = tid & 31;
    const float* hr = hin + (size_t)row * DD;

    float4 x = *(const float4*)(hr + (tid << 2));
    float s = x.x + x.y + x.z + x.w;
    s = warp_sum(s);
    if (lane == 0) red[wid] = s;
    __syncthreads();
    float mu = (red[0] + red[1] + red[2] + red[3]) * (1.0f / DD);
    __syncthreads();

    float d0 = x.x - mu, d1 = x.y - mu, d2 = x.z - mu, d3 = x.w - mu;
    float vs = d0 * d0 + d1 * d1 + d2 * d2 + d3 * d3;
    vs = warp_sum(vs);
    if (lane == 0) red[wid] = vs;
    __syncthreads();
    float var = (red[0] + red[1] + red[2] + red[3]) * (1.0f / DD);
    float inv = rsqrtf(var + 1e-5f);

    float4 g4 = *(const float4*)(gw + (tid << 2));
    float4 b4 = *(const float4*)(gb + (tid << 2));
    float4 o;
    o.x = d0 * inv * g4.x + b4.x;
    o.y = d1 * inv * g4.y + b4.y;
    o.z = d2 * inv * g4.z + b4.z;
    o.w = d3 * inv * g4.w + b4.w;
    *(float4*)(out + (size_t)row * DD + (tid << 2)) = o;
}

// ---------------------------------------------------------------------------
// Host launcher: edgebias3 forked to a side stream (overlaps transposes +
// in-gemm + QKV0); joined before the first attention.
// ---------------------------------------------------------------------------
extern "C" void kernel_launch(void* const* d_in, const int* in_sizes, int n_in,
                              void* d_out, int out_size)
{
    const float* x     = (const float*)d_in[0];
    const float* edges = (const float*)d_in[1];
    const float* in_w  = (const float*)d_in[2];
    const float* in_b  = (const float*)d_in[3];
    const float* qw    = (const float*)d_in[4];
    const float* qb    = (const float*)d_in[5];
    const float* kw    = (const float*)d_in[6];
    const float* kb    = (const float*)d_in[7];
    const float* vw    = (const float*)d_in[8];
    const float* vb    = (const float*)d_in[9];
    const float* ow    = (const float*)d_in[10];
    const float* ob    = (const float*)d_in[11];
    const float* ew    = (const float*)d_in[12];
    // d_in[13] = eb: constant over j, cancels in softmax -> unused
    const float* ln_g  = (const float*)d_in[14];
    const float* ln_b  = (const float*)d_in[15];

    void* sp = nullptr;
    cudaGetSymbolAddress(&sp, g_scratch);
    unsigned char* base = (unsigned char*)sp;
    float*  h    = (float*)base;                          // 8 MB
    __half* qh   = (__half*)(base + 8388608);
    __half* kh   = qh  + (size_t)MTOT * DD;
    __half* vth  = kh  + (size_t)MTOT * DD;
    __half* atth = vth + (size_t)MTOT * DD;
    __half* wh_in = atth + (size_t)MTOT * DD;             // [512][128]
    __half* wh_q  = wh_in + 512 * 128;                    // [3][512][512]
    __half* wh_k  = wh_q + 3 * 512 * 512;
    __half* wh_v  = wh_k + 3 * 512 * 512;
    __half* wh_o  = wh_v + 3 * 512 * 512;
    __half* ebias = wh_o + 3 * 512 * 512;                 // [3][BB*HH][NN][NN]

    cudaFuncSetAttribute(attn_h,
                         cudaFuncAttributeMaxDynamicSharedMemorySize,
                         ATTN_SMEM);

    // fork: edgebias3 on a side stream
    cudaStream_t s2;
    cudaStreamCreateWithFlags(&s2, cudaStreamNonBlocking);
    cudaEvent_t ev1, ev2;
    cudaEventCreateWithFlags(&ev1, cudaEventDisableTiming);
    cudaEventCreateWithFlags(&ev2, cudaEventDisableTiming);
    cudaEventRecord(ev1, 0);
    cudaStreamWaitEvent(s2, ev1, 0);
    edgebias3<<<dim3(NN, BB), 256, 0, s2>>>(edges, ew, ebias);
    cudaEventRecord(ev2, s2);

    transpose_w<<<dim3(16, 4, 1), 256>>>(in_w, wh_in, 128, 512);
    transpose_w4<<<dim3(16, 16, 12), 256>>>(qw, kw, vw, ow,
                                            wh_q, wh_k, wh_v, wh_o);

    dim3 gg(4, 32, 1);      // BM=128 grids
    dim3 g3(4, 64, 3);      // BM=64 fused-QKV grid (768 blocks)
    dim3 ga(HH, NN / 128, BB);

    gemm_h<0, 0><<<gg, 256>>>(x, wh_in, wh_in, wh_in, in_b, in_b, in_b,
                              h, h, h, nullptr, 128, 0, -1, 1.0f);

    for (int l = 0; l < LL; l++) {
        const __half* whq = wh_q + (size_t)l * 512 * 512;
        const __half* whk = wh_k + (size_t)l * 512 * 512;
        const __half* whv = wh_v + (size_t)l * 512 * 512;
        const __half* who = wh_o + (size_t)l * 512 * 512;
        const float* qbl = qb + (size_t)l * DD;
        const float* kbl = kb + (size_t)l * DD;
        const float* vbl = vb + (size_t)l * DD;
        const float* obl = ob + (size_t)l * DD;

        gemm_h<0, 1><<<g3, 256>>>(h, whq, whk, whv, qbl, kbl, vbl,
                                  qh, kh, vth, nullptr, 512, 1, 2,
                                  0.125f * LOG2E);

        if (l == 0) cudaStreamWaitEvent(0, ev2, 0);   // ebias ready
        attn_h<<<ga, 256, ATTN_SMEM>>>(qh, kh, vth,
                                       ebias + (size_t)l * EBPLANE, atth);

        gemm_h<1, 0><<<gg, 256>>>(atth, who, who, who, obl, obl, obl,
                                  h, h, h, h, 512, 0, -1, 1.0f);
    }

    ln_kernel<<<MTOT, 128>>>(h, ln_g, ln_b, (float*)d_out);

    cudaEventDestroy(ev1);
    cudaEventDestroy(ev2);
    cudaStreamDestroy(s2);
}

// round 15
// speedup vs baseline: 1.0069x; 1.0069x over previous
#include <cuda_runtime.h>
#include <cuda_fp16.h>
#include <math.h>

// Problem constants
#define BB    4
#define NN    1024
#define DD    512
#define HH    8
#define HDIM  64
#define EE    4
#define LL    3
#define MTOT  (BB*NN)   // 4096

#define EBPLANE ((size_t)BB*HH*NN*NN)   // elements per layer bias plane
#define LOG2E 1.44269504f

// Scratch: h fp32 8MB | q,k,vt,att half 16MB | weights ~6.4MB | 3 bias planes 201MB
__device__ __align__(256) unsigned char g_scratch[232914944];

// ---------------------------------------------------------------------------
// Helpers
// ---------------------------------------------------------------------------
__device__ __forceinline__ unsigned packh2(float lo, float hi) {
    __half2 h = __floats2half2_rn(lo, hi);
    return *reinterpret_cast<unsigned*>(&h);
}

__device__ __forceinline__ void mma_f16(float c[4], const unsigned a[4],
                                        unsigned b0, unsigned b1) {
    asm volatile(
        "mma.sync.aligned.m16n8k16.row.col.f32.f16.f16.f32 "
        "{%0,%1,%2,%3}, {%4,%5,%6,%7}, {%8,%9}, {%0,%1,%2,%3};\n"
        : "+f"(c[0]), "+f"(c[1]), "+f"(c[2]), "+f"(c[3])
        : "r"(a[0]), "r"(a[1]), "r"(a[2]), "r"(a[3]), "r"(b0), "r"(b1));
}

__device__ __forceinline__ void cp16(unsigned dst, const void* src) {
    asm volatile("cp.async.cg.shared.global [%0], [%1], 16;\n"
                 :: "r"(dst), "l"(src));
}
#define CP_COMMIT() asm volatile("cp.async.commit_group;\n" ::: "memory")
#define CP_WAIT(N)  asm volatile("cp.async.wait_group %0;\n" :: "n"(N) : "memory")

// ---------------------------------------------------------------------------
// Weight transpose + fp16 convert: dst[n][k] = (half)src[k][n], 32x32 tiles
// ---------------------------------------------------------------------------
__device__ __forceinline__ void transpose_body(
    const float* __restrict__ src, __half* __restrict__ dst, int K, int N)
{
    __shared__ float t[32][33];
    const int k0 = blockIdx.y * 32, n0 = blockIdx.x * 32;
    const int c = threadIdx.x & 31, r0 = threadIdx.x >> 5;
#pragma unroll
    for (int i = 0; i < 4; i++) {
        int r = r0 + i * 8;
        t[r][c] = src[(size_t)(k0 + r) * N + n0 + c];
    }
    __syncthreads();
#pragma unroll
    for (int i = 0; i < 4; i++) {
        int r = r0 + i * 8;
        dst[(size_t)(n0 + r) * K + k0 + c] = __float2half(t[c][r]);
    }
}

__global__ void transpose_w(const float* __restrict__ src,
                            __half* __restrict__ dst, int K, int N)
{
    transpose_body(src, dst, K, N);
}

__global__ void transpose_w4(
    const float* __restrict__ sq, const float* __restrict__ sk,
    const float* __restrict__ sv, const float* __restrict__ so,
    __half* __restrict__ dq, __half* __restrict__ dk,
    __half* __restrict__ dv, __half* __restrict__ dw)
{
    const int z = blockIdx.z, g = z / 3, l = z % 3;
    const size_t off = (size_t)l * DD * DD;
    const float* src = ((g == 0) ? sq : (g == 1) ? sk : (g == 2) ? sv : so) + off;
    __half* dst = ((g == 0) ? dq : (g == 1) ? dk : (g == 2) ? dv : dw) + off;
    transpose_body(src, dst, DD, DD);
}

// ---------------------------------------------------------------------------
// Fused edge-bias precompute for ALL 3 layers, scaled by LOG2E
// ---------------------------------------------------------------------------
__global__ __launch_bounds__(256) void edgebias3(
    const float* __restrict__ edges, const float* __restrict__ ew,
    __half* __restrict__ eb)
{
    __shared__ float sew[LL * EE * HH];   // 96
    const int tid = threadIdx.x;
    if (tid < LL * EE * HH) sew[tid] = ew[tid] * LOG2E;
    __syncthreads();
    const int i = blockIdx.x, b = blockIdx.y;
    const int j0 = tid << 2;
    const float* ep = edges + (((size_t)b * NN + i) * NN + j0) * EE;
    float4 e[4];
#pragma unroll
    for (int t = 0; t < 4; t++) e[t] = *(const float4*)(ep + t * EE);
#pragma unroll
    for (int l = 0; l < LL; l++) {
        const float* w = sew + l * EE * HH;
#pragma unroll
        for (int hh = 0; hh < HH; hh++) {
            const float w0 = w[0 * HH + hh], w1 = w[1 * HH + hh];
            const float w2 = w[2 * HH + hh], w3 = w[3 * HH + hh];
            float bv[4];
#pragma unroll
            for (int t = 0; t < 4; t++)
                bv[t] = e[t].x * w0 + e[t].y * w1 + e[t].z * w2 + e[t].w * w3;
            __half* dst = eb + (size_t)l * EBPLANE +
                          (((size_t)(b * HH + hh)) * NN + i) * NN + j0;
            *(uint2*)dst =
                make_uint2(packh2(bv[0], bv[1]), packh2(bv[2], bv[3]));
        }
    }
}

// ---------------------------------------------------------------------------
// fp16 GEMM: C[M,512] = A[M,K] @ Wh^T + bias (+resid), optional scale.
// BM = MHALF?64:128, BN=128, BK=32. 8 warps; warp tile (BM/4) x 64.
// MHALF=1: fr (0..63) already covers all 64 A-rows; second store dropped.
// (Verbatim R13 gemm_h, which passed with bit-identical rel_err.)
// ---------------------------------------------------------------------------
#define AST 24
#define TWORDS (128*AST)

template<int AHALF, int MHALF>
__global__ __launch_bounds__(256, 2) void gemm_h(
    const void* __restrict__ Av,
    const __half* __restrict__ Wh0, const __half* __restrict__ Wh1,
    const __half* __restrict__ Wh2,
    const float* __restrict__ bs0, const float* __restrict__ bs1,
    const float* __restrict__ bs2,
    void* __restrict__ C0, void* __restrict__ C1, void* __restrict__ C2,
    const float* __restrict__ resid, int K, int chalf, int tindex,
    float scl0)
{
    __shared__ unsigned As[2][TWORDS];
    __shared__ unsigned Bs[2][TWORDS];

    const int z = blockIdx.z;
    const __half* Wh   = (z == 0) ? Wh0 : (z == 1) ? Wh1 : Wh2;
    const float*  bias = (z == 0) ? bs0 : (z == 1) ? bs1 : bs2;
    void*         C    = (z == 0) ? C0  : (z == 1) ? C1  : C2;
    const float   sc   = (z == 0) ? scl0 : 1.0f;

    const int tid = threadIdx.x;
    const int wid = tid >> 5, lane = tid & 31;
    const int wm = wid & 3, wn = wid >> 2;
    const int qr = lane >> 2, qc = lane & 3;
    const int BMv = MHALF ? 64 : 128;
    const int m0 = blockIdx.y * BMv, n0 = blockIdx.x * 128;
    const int KS = K >> 5;
    const int wmb = MHALF ? wm * 16 : wm * 32;
    const int NMF = MHALF ? 1 : 2;

    const int hr = tid >> 1, hg = tid & 1;
    const int fr = tid >> 2, fg = (tid >> 1) & 1, fq = tid & 1;

    float4 aA0, aB0, aA1, aB1;
    uint4  aL1, aL2;
    uint4  bL1, bL2;

#define LOAD_STAGE(k0)                                                        \
    do {                                                                      \
        if (AHALF) {                                                          \
            const __half* Ah = (const __half*)Av +                            \
                (size_t)(m0 + hr) * K + (k0) + hg * 16;                       \
            aL1 = *(const uint4*)Ah; aL2 = *(const uint4*)(Ah + 8);           \
        } else {                                                              \
            const float* Af = (const float*)Av +                              \
                (size_t)(m0 + fr) * K + (k0) + fg * 16 + fq * 4;              \
            aA0 = *(const float4*)Af; aB0 = *(const float4*)(Af + 8);         \
            if (!MHALF) {                                                     \
                const float* Ag = Af + (size_t)64 * K;                        \
                aA1 = *(const float4*)Ag; aB1 = *(const float4*)(Ag + 8);     \
            }                                                                 \
        }                                                                     \
        const __half* Bp = Wh + (size_t)(n0 + hr) * K + (k0) + hg * 16;       \
        bL1 = *(const uint4*)Bp; bL2 = *(const uint4*)(Bp + 8);               \
    } while (0)

#define STORE_STAGE(buf)                                                      \
    do {                                                                      \
        if (AHALF) {                                                          \
            unsigned* p = &As[buf][hr * AST + hg * 8];                        \
            *(uint2*)(p + 0) = make_uint2(aL1.x, aL2.x);                      \
            *(uint2*)(p + 2) = make_uint2(aL1.y, aL2.y);                      \
            *(uint2*)(p + 4) = make_uint2(aL1.z, aL2.z);                      \
            *(uint2*)(p + 6) = make_uint2(aL1.w, aL2.w);                      \
        } else {                                                              \
            *(uint4*)&As[buf][fr * AST + fg * 8 + fq * 4] =                   \
                make_uint4(packh2(aA0.x, aA0.y), packh2(aB0.x, aB0.y),        \
                           packh2(aA0.z, aA0.w), packh2(aB0.z, aB0.w));       \
            if (!MHALF)                                                       \
                *(uint4*)&As[buf][(fr + 64) * AST + fg * 8 + fq * 4] =        \
                    make_uint4(packh2(aA1.x, aA1.y), packh2(aB1.x, aB1.y),    \
                               packh2(aA1.z, aA1.w), packh2(aB1.z, aB1.w));   \
        }                                                                     \
        unsigned* bp = &Bs[buf][hr * AST + hg * 8];                           \
        *(uint2*)(bp + 0) = make_uint2(bL1.x, bL2.x);                         \
        *(uint2*)(bp + 2) = make_uint2(bL1.y, bL2.y);                         \
        *(uint2*)(bp + 4) = make_uint2(bL1.z, bL2.z);                         \
        *(uint2*)(bp + 6) = make_uint2(bL1.w, bL2.w);                         \
    } while (0)

    LOAD_STAGE(0);
    STORE_STAGE(0);
    __syncthreads();

    float acc[MHALF ? 1 : 2][8][4] = {};

    for (int ks = 0; ks < KS; ks++) {
        const int nxt = ks + 1;
        if (nxt < KS) LOAD_STAGE(nxt << 5);

        const unsigned* Ab = As[ks & 1];
        const unsigned* Bb = Bs[ks & 1];
#pragma unroll
        for (int k16 = 0; k16 < 2; k16++) {
            unsigned af[MHALF ? 1 : 2][4];
#pragma unroll
            for (int mf = 0; mf < NMF; mf++) {
                const unsigned* ap =
                    &Ab[(wmb + mf * 16 + qr) * AST + k16 * 8 + 2 * qc];
                uint2 lo = *(const uint2*)ap;
                uint2 hi = *(const uint2*)(ap + 8 * AST);
                af[mf][0] = lo.x; af[mf][1] = hi.x;
                af[mf][2] = lo.y; af[mf][3] = hi.y;
            }
#pragma unroll
            for (int nf = 0; nf < 8; nf++) {
                uint2 bb = *(const uint2*)
                    &Bb[(wn * 64 + nf * 8 + qr) * AST + k16 * 8 + 2 * qc];
                mma_f16(acc[0][nf], af[0], bb.x, bb.y);
                if (!MHALF) mma_f16(acc[1][nf], af[1], bb.x, bb.y);
            }
        }
        if (nxt < KS) {
            __syncthreads();
            STORE_STAGE(nxt & 1);
            __syncthreads();
        }
    }

    const bool transp = (chalf && z == tindex);
#pragma unroll
    for (int mf = 0; mf < NMF; mf++) {
#pragma unroll
        for (int nf = 0; nf < 8; nf++) {
            const int col = n0 + wn * 64 + nf * 8 + 2 * qc;
            const float b0 = bias[col], b1 = bias[col + 1];
#pragma unroll
            for (int rr = 0; rr < 2; rr++) {
                const int row = m0 + wmb + mf * 16 + qr + rr * 8;
                float o0 = (acc[mf][nf][rr * 2 + 0] + b0) * sc;
                float o1 = (acc[mf][nf][rr * 2 + 1] + b1) * sc;
                if (!chalf) {
                    float* Cf = (float*)C;
                    if (resid) {
                        const float* rp = resid + (size_t)row * DD + col;
                        o0 += rp[0]; o1 += rp[1];
                    }
                    *(float2*)(Cf + (size_t)row * DD + col) =
                        make_float2(o0, o1);
                } else if (transp) {
                    // vt[col][perm(row)] - permute along token dimension
                    const int wr = row >> 1, ww = wr & 7;
                    const int pww = 2 * (ww & 3) + (ww >> 2);
                    const int prow = ((wr & ~7) + pww) * 2 + (row & 1);
                    __half* Ch = (__half*)C;
                    Ch[(size_t)col * MTOT + prow]       = __float2half(o0);
                    Ch[(size_t)(col + 1) * MTOT + prow] = __float2half(o1);
                } else {
                    __half* Ch = (__half*)C;
                    const int lw = nf * 4 + qc;
                    const int pw = 2 * (lw & 3) + ((lw & 4) >> 2);
                    const int pcol = n0 + wn * 64 + ((lw & ~7) + pw) * 2;
                    __half2 hv = __floats2half2_rn(o0, o1);
                    *(__half2*)(Ch + (size_t)row * DD + pcol) = hv;
                }
            }
        }
    }
#undef LOAD_STAGE
#undef STORE_STAGE
}

// ---------------------------------------------------------------------------
// fp16 flash attention (R12 winner, unchanged): cp.async double-buffered K/V,
// exp2-domain softmax w/o max tracking, P entirely in registers.
// ---------------------------------------------------------------------------
#define QST 40
#define KVW (64*QST)
#define ATTN_SMEM ((128*QST + 4*KVW) * 4)   // 61440 B

__global__ __launch_bounds__(256, 2) void attn_h(
    const __half* __restrict__ q, const __half* __restrict__ k,
    const __half* __restrict__ vt, const __half* __restrict__ eb,
    __half* __restrict__ out)
{
    extern __shared__ unsigned smx[];
    unsigned* Qs = smx;                    // [128][QST]
    unsigned* Ks = Qs + 128 * QST;         // [2][64][QST]
    unsigned* Vs = Ks + 2 * KVW;           // [2][64][QST]

    const int h = blockIdx.x, it = blockIdx.y, b = blockIdx.z;
    const int i0 = it << 7;
    const int tid = threadIdx.x;
    const int w = tid >> 5, lane = tid & 31;
    const int qr = lane >> 2, qc = lane & 3;

    const __half* qbase = q + (size_t)(b * NN + i0) * DD + h * HDIM;
    const __half* kbase = k + (size_t)(b * NN) * DD + h * HDIM;
    const __half* vtb = vt + (size_t)(h * HDIM) * MTOT + b * NN;

    const unsigned qs_b = (unsigned)__cvta_generic_to_shared(Qs);
    const unsigned ks_b = (unsigned)__cvta_generic_to_shared(Ks);
    const unsigned vs_b = (unsigned)__cvta_generic_to_shared(Vs);

    const int lrow = tid >> 2, lg = tid & 3;

#pragma unroll
    for (int i = 0; i < 2; i++) {
        const int t = tid + i * 256;
        const int row = t >> 2, g = t & 3;
        unsigned d = qs_b + (row * QST + g * 8) * 4;
        const __half* s = qbase + (size_t)row * DD + g * 16;
        cp16(d, s); cp16(d + 16, s + 8);
    }
    CP_COMMIT();
    {
        unsigned kd = ks_b + (lrow * QST + lg * 8) * 4;
        const __half* ksrc = kbase + (size_t)lrow * DD + lg * 16;
        cp16(kd, ksrc); cp16(kd + 16, ksrc + 8);
        unsigned vd = vs_b + (lrow * QST + lg * 8) * 4;
        const __half* vsrc = vtb + (size_t)lrow * MTOT + lg * 16;
        cp16(vd, vsrc); cp16(vd + 16, vsrc + 8);
    }
    CP_COMMIT();

    CP_WAIT(1);
    __syncthreads();

    unsigned qf[4][4];
#pragma unroll
    for (int g = 0; g < 4; g++) {
        const unsigned* qp = &Qs[(w * 16 + qr) * QST + g * 8 + 2 * qc];
        uint2 lo = *(const uint2*)qp;
        uint2 hi = *(const uint2*)(qp + 8 * QST);
        qf[g][0] = lo.x; qf[g][1] = hi.x;
        qf[g][2] = lo.y; qf[g][3] = hi.y;
    }

    float l0v = 0.f, l1v = 0.f;
    float of[8][4] = {};

    const int gi = i0 + w * 16 + qr;
    const __half* bp0 = eb + ((size_t)(b * HH + h) * NN + gi) * NN + 2 * qc;
    const __half* bp1 = bp0 + (size_t)8 * NN;

    for (int jt = 0; jt < 16; jt++) {
        const int j0 = jt << 6;
        CP_WAIT(0);
        __syncthreads();

        if (jt < 15) {
            const int st = (jt + 1) & 1;
            unsigned kd = ks_b + (st * KVW + lrow * QST + lg * 8) * 4;
            const __half* ksrc = kbase + (size_t)(j0 + 64 + lrow) * DD + lg * 16;
            cp16(kd, ksrc); cp16(kd + 16, ksrc + 8);
            unsigned vd = vs_b + (st * KVW + lrow * QST + lg * 8) * 4;
            const __half* vsrc = vtb + (size_t)lrow * MTOT + j0 + 64 + lg * 16;
            cp16(vd, vsrc); cp16(vd + 16, vsrc + 8);
            CP_COMMIT();
        }

        const unsigned* Kst = Ks + (jt & 1) * KVW;
        const unsigned* Vst = Vs + (jt & 1) * KVW;

        __half2 Bv0[8], Bv1[8];
#pragma unroll
        for (int n8 = 0; n8 < 8; n8++) {
            Bv0[n8] = *(const __half2*)(bp0 + j0 + n8 * 8);
            Bv1[n8] = *(const __half2*)(bp1 + j0 + n8 * 8);
        }

        // ---- S = Q K^T (log2 domain) + bias; p = exp2(S); pack to regs ----
        unsigned pf[8][2];
#pragma unroll
        for (int n8 = 0; n8 < 8; n8++) {
            float sd[4] = {};
            const unsigned* kp = &Kst[(n8 * 8 + qr) * QST + 2 * qc];
#pragma unroll
            for (int g = 0; g < 4; g++) {
                uint2 bb = *(const uint2*)(kp + g * 8);
                mma_f16(sd, qf[g], bb.x, bb.y);
            }
            float2 f0 = __half22float2(Bv0[n8]);
            float2 f1 = __half22float2(Bv1[n8]);
            float p0 = exp2f(sd[0] + f0.x);
            float p1 = exp2f(sd[1] + f0.y);
            float p2 = exp2f(sd[2] + f1.x);
            float p3 = exp2f(sd[3] + f1.y);
            l0v += p0 + p1;
            l1v += p2 + p3;
            pf[n8][0] = packh2(p0, p1);
            pf[n8][1] = packh2(p2, p3);
        }

        // ---- O += P @ V  (A-fragments straight from pf registers) ----
#pragma unroll
        for (int g = 0; g < 4; g++) {
            unsigned af[4];
            af[0] = pf[2 * g][0];
            af[1] = pf[2 * g][1];
            af[2] = pf[2 * g + 1][0];
            af[3] = pf[2 * g + 1][1];
#pragma unroll
            for (int n8 = 0; n8 < 8; n8++) {
                uint2 vv = *(const uint2*)
                    &Vst[(n8 * 8 + qr) * QST + g * 8 + 2 * qc];
                mma_f16(of[n8], af, vv.x, vv.y);
            }
        }
    }

    l0v += __shfl_xor_sync(0xffffffffu, l0v, 1);
    l0v += __shfl_xor_sync(0xffffffffu, l0v, 2);
    l1v += __shfl_xor_sync(0xffffffffu, l1v, 1);
    l1v += __shfl_xor_sync(0xffffffffu, l1v, 2);

    __half* obase = out + (size_t)(b * NN + i0 + w * 16 + qr) * DD + h * HDIM;
    const float inv0 = 1.0f / l0v, inv1 = 1.0f / l1v;
#pragma unroll
    for (int n8 = 0; n8 < 8; n8++) {
        const int col = n8 * 8 + (qc << 1);
        *(__half2*)(obase + col) =
            __floats2half2_rn(of[n8][0] * inv0, of[n8][1] * inv0);
        *(__half2*)(obase + (size_t)8 * DD + col) =
            __floats2half2_rn(of[n8][2] * inv1, of[n8][3] * inv1);
    }
}

// ---------------------------------------------------------------------------
// Row LayerNorm
// ---------------------------------------------------------------------------
__device__ __forceinline__ float warp_sum(float s) {
#pragma unroll
    for (int o = 16; o; o >>= 1) s += __shfl_xor_sync(0xffffffffu, s, o);
    return s;
}

__global__ __launch_bounds__(128) void ln_kernel(
    const float* __restrict__ hin, const float* __restrict__ gw,
    const float* __restrict__ gb, float* __restrict__ out)
{
    __shared__ float red[4];
    const int row = blockIdx.x;
    const int tid = threadIdx.x;
    const int wid = tid >> 5, lane = tid & 31;
    const float* hr = hin + (size_t)row * DD;

    float4 x = *(const float4*)(hr + (tid << 2));
    float s = x.x + x.y + x.z + x.w;
    s = warp_sum(s);
    if (lane == 0) red[wid] = s;
    __syncthreads();
    float mu = (red[0] + red[1] + red[2] + red[3]) * (1.0f / DD);
    __syncthreads();

    float d0 = x.x - mu, d1 = x.y - mu, d2 = x.z - mu, d3 = x.w - mu;
    float vs = d0 * d0 + d1 * d1 + d2 * d2 + d3 * d3;
    vs = warp_sum(vs);
    if (lane == 0) red[wid] = vs;
    __syncthreads();
    float var = (red[0] + red[1] + red[2] + red[3]) * (1.0f / DD);
    float inv = rsqrtf(var + 1e-5f);

    float4 g4 = *(const float4*)(gw + (tid << 2));
    float4 b4 = *(const float4*)(gb + (tid << 2));
    float4 o;
    o.x = d0 * inv * g4.x + b4.x;
    o.y = d1 * inv * g4.y + b4.y;
    o.z = d2 * inv * g4.z + b4.z;
    o.w = d3 * inv * g4.w + b4.w;
    *(float4*)(out + (size_t)row * DD + (tid << 2)) = o;
}

// ---------------------------------------------------------------------------
// Host launcher: SINGLE stream; QKV uses BM=64 variant.
// ---------------------------------------------------------------------------
extern "C" void kernel_launch(void* const* d_in, const int* in_sizes, int n_in,
                              void* d_out, int out_size)
{
    const float* x     = (const float*)d_in[0];
    const float* edges = (const float*)d_in[1];
    const float* in_w  = (const float*)d_in[2];
    const float* in_b  = (const float*)d_in[3];
    const float* qw    = (const float*)d_in[4];
    const float* qb    = (const float*)d_in[5];
    const float* kw    = (const float*)d_in[6];
    const float* kb    = (const float*)d_in[7];
    const float* vw    = (const float*)d_in[8];
    const float* vb    = (const float*)d_in[9];
    const float* ow    = (const float*)d_in[10];
    const float* ob    = (const float*)d_in[11];
    const float* ew    = (const float*)d_in[12];
    // d_in[13] = eb: constant over j, cancels in softmax -> unused
    const float* ln_g  = (const float*)d_in[14];
    const float* ln_b  = (const float*)d_in[15];

    void* sp = nullptr;
    cudaGetSymbolAddress(&sp, g_scratch);
    unsigned char* base = (unsigned char*)sp;
    float*  h    = (float*)base;                          // 8 MB
    __half* qh   = (__half*)(base + 8388608);
    __half* kh   = qh  + (size_t)MTOT * DD;
    __half* vth  = kh  + (size_t)MTOT * DD;
    __half* atth = vth + (size_t)MTOT * DD;
    __half* wh_in = atth + (size_t)MTOT * DD;             // [512][128]
    __half* wh_q  = wh_in + 512 * 128;                    // [3][512][512]
    __half* wh_k  = wh_q + 3 * 512 * 512;
    __half* wh_v  = wh_k + 3 * 512 * 512;
    __half* wh_o  = wh_v + 3 * 512 * 512;
    __half* ebias = wh_o + 3 * 512 * 512;                 // [3][BB*HH][NN][NN]

    cudaFuncSetAttribute(attn_h,
                         cudaFuncAttributeMaxDynamicSharedMemorySize,
                         ATTN_SMEM);

    transpose_w<<<dim3(16, 4, 1), 256>>>(in_w, wh_in, 128, 512);
    transpose_w4<<<dim3(16, 16, 12), 256>>>(qw, kw, vw, ow,
                                            wh_q, wh_k, wh_v, wh_o);
    edgebias3<<<dim3(NN, BB), 256>>>(edges, ew, ebias);

    dim3 gg(4, 32, 1);      // BM=128 grids
    dim3 g3(4, 64, 3);      // BM=64 fused-QKV grid (768 blocks)
    dim3 ga(HH, NN / 128, BB);

    gemm_h<0, 0><<<gg, 256>>>(x, wh_in, wh_in, wh_in, in_b, in_b, in_b,
                              h, h, h, nullptr, 128, 0, -1, 1.0f);

    for (int l = 0; l < LL; l++) {
        const __half* whq = wh_q + (size_t)l * 512 * 512;
        const __half* whk = wh_k + (size_t)l * 512 * 512;
        const __half* whv = wh_v + (size_t)l * 512 * 512;
        const __half* who = wh_o + (size_t)l * 512 * 512;
        const float* qbl = qb + (size_t)l * DD;
        const float* kbl = kb + (size_t)l * DD;
        const float* vbl = vb + (size_t)l * DD;
        const float* obl = ob + (size_t)l * DD;

        gemm_h<0, 1><<<g3, 256>>>(h, whq, whk, whv, qbl, kbl, vbl,
                                  qh, kh, vth, nullptr, 512, 1, 2,
                                  0.125f * LOG2E);

        attn_h<<<ga, 256, ATTN_SMEM>>>(qh, kh, vth,
                                       ebias + (size_t)l * EBPLANE, atth);

        gemm_h<1, 0><<<gg, 256>>>(atth, who, who, who, obl, obl, obl,
                                  h, h, h, h, 512, 0, -1, 1.0f);
    }

    ln_kernel<<<MTOT, 128>>>(h, ln_g, ln_b, (float*)d_out);
}

// round 17
// speedup vs baseline: 1.1286x; 1.1209x over previous
#include <cuda_runtime.h>
#include <cuda_fp16.h>
#include <math.h>

// Problem constants
#define BB    4
#define NN    1024
#define DD    512
#define HH    8
#define HDIM  64
#define EE    4
#define LL    3
#define MTOT  (BB*NN)   // 4096

#define EBPLANE ((size_t)BB*HH*NN*NN)   // elements per layer bias plane
#define LOG2E 1.44269504f

// Scratch: h fp32 8MB | q,k,vt,att half 16MB | weights ~6.4MB | 3 bias planes 201MB
__device__ __align__(256) unsigned char g_scratch[232914944];

// ---------------------------------------------------------------------------
// Helpers
// ---------------------------------------------------------------------------
__device__ __forceinline__ unsigned packh2(float lo, float hi) {
    __half2 h = __floats2half2_rn(lo, hi);
    return *reinterpret_cast<unsigned*>(&h);
}

__device__ __forceinline__ void mma_f16(float c[4], const unsigned a[4],
                                        unsigned b0, unsigned b1) {
    asm volatile(
        "mma.sync.aligned.m16n8k16.row.col.f32.f16.f16.f32 "
        "{%0,%1,%2,%3}, {%4,%5,%6,%7}, {%8,%9}, {%0,%1,%2,%3};\n"
        : "+f"(c[0]), "+f"(c[1]), "+f"(c[2]), "+f"(c[3])
        : "r"(a[0]), "r"(a[1]), "r"(a[2]), "r"(a[3]), "r"(b0), "r"(b1));
}

__device__ __forceinline__ void cp16(unsigned dst, const void* src) {
    asm volatile("cp.async.cg.shared.global [%0], [%1], 16;\n"
                 :: "r"(dst), "l"(src));
}
#define CP_COMMIT() asm volatile("cp.async.commit_group;\n" ::: "memory")
#define CP_WAIT(N)  asm volatile("cp.async.wait_group %0;\n" :: "n"(N) : "memory")

// ---------------------------------------------------------------------------
// Weight transpose + fp16 convert: dst[n][k] = (half)src[k][n], 32x32 tiles
// ---------------------------------------------------------------------------
__device__ __forceinline__ void transpose_body(
    const float* __restrict__ src, __half* __restrict__ dst, int K, int N)
{
    __shared__ float t[32][33];
    const int k0 = blockIdx.y * 32, n0 = blockIdx.x * 32;
    const int c = threadIdx.x & 31, r0 = threadIdx.x >> 5;
#pragma unroll
    for (int i = 0; i < 4; i++) {
        int r = r0 + i * 8;
        t[r][c] = src[(size_t)(k0 + r) * N + n0 + c];
    }
    __syncthreads();
#pragma unroll
    for (int i = 0; i < 4; i++) {
        int r = r0 + i * 8;
        dst[(size_t)(n0 + r) * K + k0 + c] = __float2half(t[c][r]);
    }
}

// z = 0..11: group g = z/3 picks Q/K/V/O weight set, l = z%3 layer slice.
// z = 12: the input projection weight (K=128), valid only for blockIdx.y < 4.
__global__ void transpose_w5(
    const float* __restrict__ sq, const float* __restrict__ sk,
    const float* __restrict__ sv, const float* __restrict__ so,
    const float* __restrict__ si,
    __half* __restrict__ dq, __half* __restrict__ dk,
    __half* __restrict__ dv, __half* __restrict__ dw,
    __half* __restrict__ di)
{
    const int z = blockIdx.z;
    if (z == 12) {
        if (blockIdx.y >= 4) return;     // K=128 -> only 4 k-tiles
        transpose_body(si, di, 128, DD);
        return;
    }
    const int g = z / 3, l = z % 3;
    const size_t off = (size_t)l * DD * DD;
    const float* src = ((g == 0) ? sq : (g == 1) ? sk : (g == 2) ? sv : so) + off;
    __half* dst = ((g == 0) ? dq : (g == 1) ? dk : (g == 2) ? dv : dw) + off;
    transpose_body(src, dst, DD, DD);
}

// ---------------------------------------------------------------------------
// Fused edge-bias precompute for ALL 3 layers, scaled by LOG2E
// ---------------------------------------------------------------------------
__global__ __launch_bounds__(256) void edgebias3(
    const float* __restrict__ edges, const float* __restrict__ ew,
    __half* __restrict__ eb)
{
    __shared__ float sew[LL * EE * HH];   // 96
    const int tid = threadIdx.x;
    if (tid < LL * EE * HH) sew[tid] = ew[tid] * LOG2E;
    __syncthreads();
    const int i = blockIdx.x, b = blockIdx.y;
    const int j0 = tid << 2;
    const float* ep = edges + (((size_t)b * NN + i) * NN + j0) * EE;
    float4 e[4];
#pragma unroll
    for (int t = 0; t < 4; t++) e[t] = *(const float4*)(ep + t * EE);
#pragma unroll
    for (int l = 0; l < LL; l++) {
        const float* w = sew + l * EE * HH;
#pragma unroll
        for (int hh = 0; hh < HH; hh++) {
            const float w0 = w[0 * HH + hh], w1 = w[1 * HH + hh];
            const float w2 = w[2 * HH + hh], w3 = w[3 * HH + hh];
            float bv[4];
#pragma unroll
            for (int t = 0; t < 4; t++)
                bv[t] = e[t].x * w0 + e[t].y * w1 + e[t].z * w2 + e[t].w * w3;
            __half* dst = eb + (size_t)l * EBPLANE +
                          (((size_t)(b * HH + hh)) * NN + i) * NN + j0;
            *(uint2*)dst =
                make_uint2(packh2(bv[0], bv[1]), packh2(bv[2], bv[3]));
        }
    }
}

// ---------------------------------------------------------------------------
// fp16 GEMM (R12-proven): C[M,512] = A[M,K] @ Wh^T + bias (+resid), scale.
// BM=128 BN=128 BK=32, 8 warps (4m x 2n), warp tile 32x64.
// ---------------------------------------------------------------------------
#define AST 24
#define TWORDS (128*AST)

template<int AHALF>
__global__ __launch_bounds__(256, 2) void gemm_h(
    const void* __restrict__ Av,
    const __half* __restrict__ Wh0, const __half* __restrict__ Wh1,
    const __half* __restrict__ Wh2,
    const float* __restrict__ bs0, const float* __restrict__ bs1,
    const float* __restrict__ bs2,
    void* __restrict__ C0, void* __restrict__ C1, void* __restrict__ C2,
    const float* __restrict__ resid, int K, int chalf, int tindex,
    float scl0)
{
    __shared__ unsigned As[2][TWORDS];
    __shared__ unsigned Bs[2][TWORDS];

    const int z = blockIdx.z;
    const __half* Wh   = (z == 0) ? Wh0 : (z == 1) ? Wh1 : Wh2;
    const float*  bias = (z == 0) ? bs0 : (z == 1) ? bs1 : bs2;
    void*         C    = (z == 0) ? C0  : (z == 1) ? C1  : C2;
    const float   sc   = (z == 0) ? scl0 : 1.0f;

    const int tid = threadIdx.x;
    const int wid = tid >> 5, lane = tid & 31;
    const int wm = wid & 3, wn = wid >> 2;
    const int qr = lane >> 2, qc = lane & 3;
    const int m0 = blockIdx.y * 128, n0 = blockIdx.x * 128;
    const int KS = K >> 5;

    const int hr = tid >> 1, hg = tid & 1;
    const int fr = tid >> 2, fg = (tid >> 1) & 1, fq = tid & 1;

    float4 aA0, aB0, aA1, aB1;
    uint4  aL1, aL2;
    uint4  bL1, bL2;

#define LOAD_STAGE(k0)                                                        \
    do {                                                                      \
        if (AHALF) {                                                          \
            const __half* Ah = (const __half*)Av +                            \
                (size_t)(m0 + hr) * K + (k0) + hg * 16;                       \
            aL1 = *(const uint4*)Ah; aL2 = *(const uint4*)(Ah + 8);           \
        } else {                                                              \
            const float* Af = (const float*)Av +                              \
                (size_t)(m0 + fr) * K + (k0) + fg * 16 + fq * 4;              \
            aA0 = *(const float4*)Af; aB0 = *(const float4*)(Af + 8);         \
            const float* Ag = Af + (size_t)64 * K;                            \
            aA1 = *(const float4*)Ag; aB1 = *(const float4*)(Ag + 8);         \
        }                                                                     \
        const __half* Bp = Wh + (size_t)(n0 + hr) * K + (k0) + hg * 16;       \
        bL1 = *(const uint4*)Bp; bL2 = *(const uint4*)(Bp + 8);               \
    } while (0)

#define STORE_STAGE(buf)                                                      \
    do {                                                                      \
        if (AHALF) {                                                          \
            unsigned* p = &As[buf][hr * AST + hg * 8];                        \
            *(uint2*)(p + 0) = make_uint2(aL1.x, aL2.x);                      \
            *(uint2*)(p + 2) = make_uint2(aL1.y, aL2.y);                      \
            *(uint2*)(p + 4) = make_uint2(aL1.z, aL2.z);                      \
            *(uint2*)(p + 6) = make_uint2(aL1.w, aL2.w);                      \
        } else {                                                              \
            *(uint4*)&As[buf][fr * AST + fg * 8 + fq * 4] =                   \
                make_uint4(packh2(aA0.x, aA0.y), packh2(aB0.x, aB0.y),        \
                           packh2(aA0.z, aA0.w), packh2(aB0.z, aB0.w));       \
            *(uint4*)&As[buf][(fr + 64) * AST + fg * 8 + fq * 4] =            \
                make_uint4(packh2(aA1.x, aA1.y), packh2(aB1.x, aB1.y),        \
                           packh2(aA1.z, aA1.w), packh2(aB1.z, aB1.w));       \
        }                                                                     \
        unsigned* bp = &Bs[buf][hr * AST + hg * 8];                           \
        *(uint2*)(bp + 0) = make_uint2(bL1.x, bL2.x);                         \
        *(uint2*)(bp + 2) = make_uint2(bL1.y, bL2.y);                         \
        *(uint2*)(bp + 4) = make_uint2(bL1.z, bL2.z);                         \
        *(uint2*)(bp + 6) = make_uint2(bL1.w, bL2.w);                         \
    } while (0)

    LOAD_STAGE(0);
    STORE_STAGE(0);
    __syncthreads();

    float acc[2][8][4] = {};

    for (int ks = 0; ks < KS; ks++) {
        const int nxt = ks + 1;
        if (nxt < KS) LOAD_STAGE(nxt << 5);

        const unsigned* Ab = As[ks & 1];
        const unsigned* Bb = Bs[ks & 1];
#pragma unroll
        for (int k16 = 0; k16 < 2; k16++) {
            unsigned af[2][4];
#pragma unroll
            for (int mf = 0; mf < 2; mf++) {
                const unsigned* ap =
                    &Ab[(wm * 32 + mf * 16 + qr) * AST + k16 * 8 + 2 * qc];
                uint2 lo = *(const uint2*)ap;
                uint2 hi = *(const uint2*)(ap + 8 * AST);
                af[mf][0] = lo.x; af[mf][1] = hi.x;
                af[mf][2] = lo.y; af[mf][3] = hi.y;
            }
#pragma unroll
            for (int nf = 0; nf < 8; nf++) {
                uint2 bb = *(const uint2*)
                    &Bb[(wn * 64 + nf * 8 + qr) * AST + k16 * 8 + 2 * qc];
                mma_f16(acc[0][nf], af[0], bb.x, bb.y);
                mma_f16(acc[1][nf], af[1], bb.x, bb.y);
            }
        }
        if (nxt < KS) {
            __syncthreads();
            STORE_STAGE(nxt & 1);
            __syncthreads();
        }
    }

    const bool transp = (chalf && z == tindex);
#pragma unroll
    for (int mf = 0; mf < 2; mf++) {
#pragma unroll
        for (int nf = 0; nf < 8; nf++) {
            const int col = n0 + wn * 64 + nf * 8 + 2 * qc;
            const float b0 = bias[col], b1 = bias[col + 1];
#pragma unroll
            for (int rr = 0; rr < 2; rr++) {
                const int row = m0 + wm * 32 + mf * 16 + qr + rr * 8;
                float o0 = (acc[mf][nf][rr * 2 + 0] + b0) * sc;
                float o1 = (acc[mf][nf][rr * 2 + 1] + b1) * sc;
                if (!chalf) {
                    float* Cf = (float*)C;
                    if (resid) {
                        const float* rp = resid + (size_t)row * DD + col;
                        o0 += rp[0]; o1 += rp[1];
                    }
                    *(float2*)(Cf + (size_t)row * DD + col) =
                        make_float2(o0, o1);
                } else if (transp) {
                    // vt[col][perm(row)] - permute along token dimension
                    const int wr = row >> 1, ww = wr & 7;
                    const int pww = 2 * (ww & 3) + (ww >> 2);
                    const int prow = ((wr & ~7) + pww) * 2 + (row & 1);
                    __half* Ch = (__half*)C;
                    Ch[(size_t)col * MTOT + prow]       = __float2half(o0);
                    Ch[(size_t)(col + 1) * MTOT + prow] = __float2half(o1);
                } else {
                    __half* Ch = (__half*)C;
                    const int lw = nf * 4 + qc;
                    const int pw = 2 * (lw & 3) + ((lw & 4) >> 2);
                    const int pcol = n0 + wn * 64 + ((lw & ~7) + pw) * 2;
                    __half2 hv = __floats2half2_rn(o0, o1);
                    *(__half2*)(Ch + (size_t)row * DD + pcol) = hv;
                }
            }
        }
    }
#undef LOAD_STAGE
#undef STORE_STAGE
}

// ---------------------------------------------------------------------------
// fp16 flash attention (R12 winner, unchanged): cp.async double-buffered K/V,
// exp2-domain softmax w/o max tracking, P entirely in registers.
// ---------------------------------------------------------------------------
#define QST 40
#define KVW (64*QST)
#define ATTN_SMEM ((128*QST + 4*KVW) * 4)   // 61440 B

__global__ __launch_bounds__(256, 2) void attn_h(
    const __half* __restrict__ q, const __half* __restrict__ k,
    const __half* __restrict__ vt, const __half* __restrict__ eb,
    __half* __restrict__ out)
{
    extern __shared__ unsigned smx[];
    unsigned* Qs = smx;                    // [128][QST]
    unsigned* Ks = Qs + 128 * QST;         // [2][64][QST]
    unsigned* Vs = Ks + 2 * KVW;           // [2][64][QST]

    const int h = blockIdx.x, it = blockIdx.y, b = blockIdx.z;
    const int i0 = it << 7;
    const int tid = threadIdx.x;
    const int w = tid >> 5, lane = tid & 31;
    const int qr = lane >> 2, qc = lane & 3;

    const __half* qbase = q + (size_t)(b * NN + i0) * DD + h * HDIM;
    const __half* kbase = k + (size_t)(b * NN) * DD + h * HDIM;
    const __half* vtb = vt + (size_t)(h * HDIM) * MTOT + b * NN;

    const unsigned qs_b = (unsigned)__cvta_generic_to_shared(Qs);
    const unsigned ks_b = (unsigned)__cvta_generic_to_shared(Ks);
    const unsigned vs_b = (unsigned)__cvta_generic_to_shared(Vs);

    const int lrow = tid >> 2, lg = tid & 3;

#pragma unroll
    for (int i = 0; i < 2; i++) {
        const int t = tid + i * 256;
        const int row = t >> 2, g = t & 3;
        unsigned d = qs_b + (row * QST + g * 8) * 4;
        const __half* s = qbase + (size_t)row * DD + g * 16;
        cp16(d, s); cp16(d + 16, s + 8);
    }
    CP_COMMIT();
    {
        unsigned kd = ks_b + (lrow * QST + lg * 8) * 4;
        const __half* ksrc = kbase + (size_t)lrow * DD + lg * 16;
        cp16(kd, ksrc); cp16(kd + 16, ksrc + 8);
        unsigned vd = vs_b + (lrow * QST + lg * 8) * 4;
        const __half* vsrc = vtb + (size_t)lrow * MTOT + lg * 16;
        cp16(vd, vsrc); cp16(vd + 16, vsrc + 8);
    }
    CP_COMMIT();

    CP_WAIT(1);
    __syncthreads();

    unsigned qf[4][4];
#pragma unroll
    for (int g = 0; g < 4; g++) {
        const unsigned* qp = &Qs[(w * 16 + qr) * QST + g * 8 + 2 * qc];
        uint2 lo = *(const uint2*)qp;
        uint2 hi = *(const uint2*)(qp + 8 * QST);
        qf[g][0] = lo.x; qf[g][1] = hi.x;
        qf[g][2] = lo.y; qf[g][3] = hi.y;
    }

    float l0v = 0.f, l1v = 0.f;
    float of[8][4] = {};

    const int gi = i0 + w * 16 + qr;
    const __half* bp0 = eb + ((size_t)(b * HH + h) * NN + gi) * NN + 2 * qc;
    const __half* bp1 = bp0 + (size_t)8 * NN;

    for (int jt = 0; jt < 16; jt++) {
        const int j0 = jt << 6;
        CP_WAIT(0);
        __syncthreads();

        if (jt < 15) {
            const int st = (jt + 1) & 1;
            unsigned kd = ks_b + (st * KVW + lrow * QST + lg * 8) * 4;
            const __half* ksrc = kbase + (size_t)(j0 + 64 + lrow) * DD + lg * 16;
            cp16(kd, ksrc); cp16(kd + 16, ksrc + 8);
            unsigned vd = vs_b + (st * KVW + lrow * QST + lg * 8) * 4;
            const __half* vsrc = vtb + (size_t)lrow * MTOT + j0 + 64 + lg * 16;
            cp16(vd, vsrc); cp16(vd + 16, vsrc + 8);
            CP_COMMIT();
        }

        const unsigned* Kst = Ks + (jt & 1) * KVW;
        const unsigned* Vst = Vs + (jt & 1) * KVW;

        __half2 Bv0[8], Bv1[8];
#pragma unroll
        for (int n8 = 0; n8 < 8; n8++) {
            Bv0[n8] = *(const __half2*)(bp0 + j0 + n8 * 8);
            Bv1[n8] = *(const __half2*)(bp1 + j0 + n8 * 8);
        }

        // ---- S = Q K^T (log2 domain) + bias; p = exp2(S); pack to regs ----
        unsigned pf[8][2];
#pragma unroll
        for (int n8 = 0; n8 < 8; n8++) {
            float sd[4] = {};
            const unsigned* kp = &Kst[(n8 * 8 + qr) * QST + 2 * qc];
#pragma unroll
            for (int g = 0; g < 4; g++) {
                uint2 bb = *(const uint2*)(kp + g * 8);
                mma_f16(sd, qf[g], bb.x, bb.y);
            }
            float2 f0 = __half22float2(Bv0[n8]);
            float2 f1 = __half22float2(Bv1[n8]);
            float p0 = exp2f(sd[0] + f0.x);
            float p1 = exp2f(sd[1] + f0.y);
            float p2 = exp2f(sd[2] + f1.x);
            float p3 = exp2f(sd[3] + f1.y);
            l0v += p0 + p1;
            l1v += p2 + p3;
            pf[n8][0] = packh2(p0, p1);
            pf[n8][1] = packh2(p2, p3);
        }

        // ---- O += P @ V  (A-fragments straight from pf registers) ----
#pragma unroll
        for (int g = 0; g < 4; g++) {
            unsigned af[4];
            af[0] = pf[2 * g][0];
            af[1] = pf[2 * g][1];
            af[2] = pf[2 * g + 1][0];
            af[3] = pf[2 * g + 1][1];
#pragma unroll
            for (int n8 = 0; n8 < 8; n8++) {
                uint2 vv = *(const uint2*)
                    &Vst[(n8 * 8 + qr) * QST + g * 8 + 2 * qc];
                mma_f16(of[n8], af, vv.x, vv.y);
            }
        }
    }

    l0v += __shfl_xor_sync(0xffffffffu, l0v, 1);
    l0v += __shfl_xor_sync(0xffffffffu, l0v, 2);
    l1v += __shfl_xor_sync(0xffffffffu, l1v, 1);
    l1v += __shfl_xor_sync(0xffffffffu, l1v, 2);

    __half* obase = out + (size_t)(b * NN + i0 + w * 16 + qr) * DD + h * HDIM;
    const float inv0 = 1.0f / l0v, inv1 = 1.0f / l1v;
#pragma unroll
    for (int n8 = 0; n8 < 8; n8++) {
        const int col = n8 * 8 + (qc << 1);
        *(__half2*)(obase + col) =
            __floats2half2_rn(of[n8][0] * inv0, of[n8][1] * inv0);
        *(__half2*)(obase + (size_t)8 * DD + col) =
            __floats2half2_rn(of[n8][2] * inv1, of[n8][3] * inv1);
    }
}

// ---------------------------------------------------------------------------
// Row LayerNorm
// ---------------------------------------------------------------------------
__device__ __forceinline__ float warp_sum(float s) {
#pragma unroll
    for (int o = 16; o; o >>= 1) s += __shfl_xor_sync(0xffffffffu, s, o);
    return s;
}

__global__ __launch_bounds__(128) void ln_kernel(
    const float* __restrict__ hin, const float* __restrict__ gw,
    const float* __restrict__ gb, float* __restrict__ out)
{
    __shared__ float red[4];
    const int row = blockIdx.x;
    const int tid = threadIdx.x;
    const int wid = tid >> 5, lane = tid & 31;
    const float* hr = hin + (size_t)row * DD;

    float4 x = *(const float4*)(hr + (tid << 2));
    float s = x.x + x.y + x.z + x.w;
    s = warp_sum(s);
    if (lane == 0) red[wid] = s;
    __syncthreads();
    float mu = (red[0] + red[1] + red[2] + red[3]) * (1.0f / DD);
    __syncthreads();

    float d0 = x.x - mu, d1 = x.y - mu, d2 = x.z - mu, d3 = x.w - mu;
    float vs = d0 * d0 + d1 * d1 + d2 * d2 + d3 * d3;
    vs = warp_sum(vs);
    if (lane == 0) red[wid] = vs;
    __syncthreads();
    float var = (red[0] + red[1] + red[2] + red[3]) * (1.0f / DD);
    float inv = rsqrtf(var + 1e-5f);

    float4 g4 = *(const float4*)(gw + (tid << 2));
    float4 b4 = *(const float4*)(gb + (tid << 2));
    float4 o;
    o.x = d0 * inv * g4.x + b4.x;
    o.y = d1 * inv * g4.y + b4.y;
    o.z = d2 * inv * g4.z + b4.z;
    o.w = d3 * inv * g4.w + b4.w;
    *(float4*)(out + (size_t)row * DD + (tid << 2)) = o;
}

// ---------------------------------------------------------------------------
// Host launcher (R12 structure: single stream; transposes merged into one)
// ---------------------------------------------------------------------------
extern "C" void kernel_launch(void* const* d_in, const int* in_sizes, int n_in,
                              void* d_out, int out_size)
{
    const float* x     = (const float*)d_in[0];
    const float* edges = (const float*)d_in[1];
    const float* in_w  = (const float*)d_in[2];
    const float* in_b  = (const float*)d_in[3];
    const float* qw    = (const float*)d_in[4];
    const float* qb    = (const float*)d_in[5];
    const float* kw    = (const float*)d_in[6];
    const float* kb    = (const float*)d_in[7];
    const float* vw    = (const float*)d_in[8];
    const float* vb    = (const float*)d_in[9];
    const float* ow    = (const float*)d_in[10];
    const float* ob    = (const float*)d_in[11];
    const float* ew    = (const float*)d_in[12];
    // d_in[13] = eb: constant over j, cancels in softmax -> unused
    const float* ln_g  = (const float*)d_in[14];
    const float* ln_b  = (const float*)d_in[15];

    void* sp = nullptr;
    cudaGetSymbolAddress(&sp, g_scratch);
    unsigned char* base = (unsigned char*)sp;
    float*  h    = (float*)base;                          // 8 MB
    __half* qh   = (__half*)(base + 8388608);
    __half* kh   = qh  + (size_t)MTOT * DD;
    __half* vth  = kh  + (size_t)MTOT * DD;
    __half* atth = vth + (size_t)MTOT * DD;
    __half* wh_in = atth + (size_t)MTOT * DD;             // [512][128]
    __half* wh_q  = wh_in + 512 * 128;                    // [3][512][512]
    __half* wh_k  = wh_q + 3 * 512 * 512;
    __half* wh_v  = wh_k + 3 * 512 * 512;
    __half* wh_o  = wh_v + 3 * 512 * 512;
    __half* ebias = wh_o + 3 * 512 * 512;                 // [3][BB*HH][NN][NN]

    cudaFuncSetAttribute(attn_h,
                         cudaFuncAttributeMaxDynamicSharedMemorySize,
                         ATTN_SMEM);

    // all weight transposes in one launch (z=0..11 big, z=12 input proj)
    transpose_w5<<<dim3(16, 16, 13), 256>>>(qw, kw, vw, ow, in_w,
                                            wh_q, wh_k, wh_v, wh_o, wh_in);
    edgebias3<<<dim3(NN, BB), 256>>>(edges, ew, ebias);

    dim3 gg(4, 32, 1);
    dim3 g3(4, 32, 3);
    dim3 ga(HH, NN / 128, BB);     // (8, 8, 4) = 256 blocks

    gemm_h<0><<<gg, 256>>>(x, wh_in, wh_in, wh_in, in_b, in_b, in_b,
                           h, h, h, nullptr, 128, 0, -1, 1.0f);

    for (int l = 0; l < LL; l++) {
        const __half* whq = wh_q + (size_t)l * 512 * 512;
        const __half* whk = wh_k + (size_t)l * 512 * 512;
        const __half* whv = wh_v + (size_t)l * 512 * 512;
        const __half* who = wh_o + (size_t)l * 512 * 512;
        const float* qbl = qb + (size_t)l * DD;
        const float* kbl = kb + (size_t)l * DD;
        const float* vbl = vb + (size_t)l * DD;
        const float* obl = ob + (size_t)l * DD;

        gemm_h<0><<<g3, 256>>>(h, whq, whk, whv, qbl, kbl, vbl,
                               qh, kh, vth, nullptr, 512, 1, 2,
                               0.125f * LOG2E);

        attn_h<<<ga, 256, ATTN_SMEM>>>(qh, kh, vth,
                                       ebias + (size_t)l * EBPLANE, atth);

        gemm_h<1><<<gg, 256>>>(atth, who, who, who, obl, obl, obl,
                               h, h, h, h, 512, 0, -1, 1.0f);
    }

    ln_kernel<<<MTOT, 128>>>(h, ln_g, ln_b, (float*)d_out);
}